// round 2
// baseline (speedup 1.0000x reference)
#include <cuda_runtime.h>

// Problem constants
#define BATCH   8192
#define DICTN   64
#define NDIM    8
#define MDIM    16
#define TPB     128      // threads per block = batch rows per block
#define TAYLOR_D 12

// out[b, s*8+i] = (expm(A[b,s]) @ x[b, s*8 .. s*8+8])[i]
// A[b,s] = sum_m c[b,m] * psi[m,s,:,:]
//
// One thread per (b, s). CTA: 128 threads share a single s (psi slice in smem,
// all shared loads are warp-broadcast / conflict-free), thread t handles
// b = blockIdx.x*128 + t.
__global__ __launch_bounds__(TPB) void transop_expm_kernel(
    const float* __restrict__ x,
    const float* __restrict__ c,
    const float* __restrict__ psi,
    float* __restrict__ out)
{
    __shared__ float psis[MDIM * 64];   // [m][e], e = i*8+j ; contiguous copy of psi[m][s][:][:]

    const int s = blockIdx.y;
    const int b = blockIdx.x * TPB + threadIdx.x;

    // Stage psi[:, s, :, :] -> smem. Global layout: psi[((m*64 + s)*8 + i)*8 + j]
    // => for fixed (m,s), 64 contiguous floats.
    for (int l = threadIdx.x; l < MDIM * 64; l += TPB) {
        const int m = l >> 6;
        const int e = l & 63;
        psis[l] = psi[(m * DICTN + s) * 64 + e];
    }
    __syncthreads();

    // Load c[b, :] (16 floats, 64B aligned). Warp-contiguous across threads.
    float cr[MDIM];
    {
        const float4* c4 = reinterpret_cast<const float4*>(c + (size_t)b * MDIM);
        #pragma unroll
        for (int q = 0; q < 4; q++) {
            float4 v = c4[q];
            cr[4*q + 0] = v.x; cr[4*q + 1] = v.y;
            cr[4*q + 2] = v.z; cr[4*q + 3] = v.w;
        }
    }

    // Build A = sum_m c[m] * psi_s[m]  (registers, 64 floats)
    float A[64];
    #pragma unroll
    for (int e = 0; e < 64; e++) A[e] = 0.0f;

    #pragma unroll
    for (int m = 0; m < MDIM; m++) {
        const float cm = cr[m];
        const float4* p4 = reinterpret_cast<const float4*>(&psis[m * 64]);
        #pragma unroll
        for (int u = 0; u < 16; u++) {
            float4 p = p4[u];              // LDS.128, warp-broadcast
            A[4*u + 0] = fmaf(cm, p.x, A[4*u + 0]);
            A[4*u + 1] = fmaf(cm, p.y, A[4*u + 1]);
            A[4*u + 2] = fmaf(cm, p.z, A[4*u + 2]);
            A[4*u + 3] = fmaf(cm, p.w, A[4*u + 3]);
        }
    }

    // Infinity norm (max abs row sum)
    float norm = 0.0f;
    #pragma unroll
    for (int i = 0; i < 8; i++) {
        float r = 0.0f;
        #pragma unroll
        for (int j = 0; j < 8; j++) r += fabsf(A[i*8 + j]);
        norm = fmaxf(norm, r);
    }

    // Scaling: pick s.t. ||A/2^sc|| <= 2
    int sc = 0;
    float nm = norm;
    while (nm > 2.0f && sc < 24) { nm *= 0.5f; sc++; }
    const float scale = __int_as_float((127 - sc) << 23);   // exact 2^-sc
    #pragma unroll
    for (int e = 0; e < 64; e++) A[e] *= scale;

    // Load x block (8 floats, 32B aligned)
    float y[8];
    {
        const float4* xb = reinterpret_cast<const float4*>(x + (size_t)b * (DICTN * NDIM) + s * NDIM);
        float4 v0 = xb[0], v1 = xb[1];
        y[0] = v0.x; y[1] = v0.y; y[2] = v0.z; y[3] = v0.w;
        y[4] = v1.x; y[5] = v1.y; y[6] = v1.z; y[7] = v1.w;
    }

    // 1/k constants for Taylor (index 1..TAYLOR_D)
    const float invk[TAYLOR_D + 1] = {
        0.0f, 1.0f, 1.0f/2, 1.0f/3, 1.0f/4, 1.0f/5, 1.0f/6,
        1.0f/7, 1.0f/8, 1.0f/9, 1.0f/10, 1.0f/11, 1.0f/12
    };

    // Apply expm(A_scaled) to y, 2^sc times:
    //   y <- sum_{k=0..D} A^k y / k!   (Horner-free running-term form)
    const int apps = 1 << sc;
    for (int a = 0; a < apps; a++) {
        float t[8];
        #pragma unroll
        for (int i = 0; i < 8; i++) t[i] = y[i];

        #pragma unroll
        for (int k = 1; k <= TAYLOR_D; k++) {
            float tn[8];
            #pragma unroll
            for (int i = 0; i < 8; i++) {
                float r = A[i*8 + 0] * t[0];
                #pragma unroll
                for (int j = 1; j < 8; j++) r = fmaf(A[i*8 + j], t[j], r);
                tn[i] = r * invk[k];
            }
            #pragma unroll
            for (int i = 0; i < 8; i++) {
                t[i] = tn[i];
                y[i] += tn[i];
            }
        }
    }

    // Store result
    {
        float4* ob = reinterpret_cast<float4*>(out + (size_t)b * (DICTN * NDIM) + s * NDIM);
        ob[0] = make_float4(y[0], y[1], y[2], y[3]);
        ob[1] = make_float4(y[4], y[5], y[6], y[7]);
    }
}

extern "C" void kernel_launch(void* const* d_in, const int* in_sizes, int n_in,
                              void* d_out, int out_size) {
    const float* x   = (const float*)d_in[0];   // (B, 512)
    const float* c   = (const float*)d_in[1];   // (B, 16)
    const float* psi = (const float*)d_in[2];   // (16, 64, 8, 8)
    float* out = (float*)d_out;                 // (B, 512)

    dim3 grid(BATCH / TPB, DICTN);              // (64, 64)
    transop_expm_kernel<<<grid, TPB>>>(x, c, psi, out);
}